// round 1
// baseline (speedup 1.0000x reference)
#include <cuda_runtime.h>
#include <cstdint>

#define T_BATCH 256
#define D_IN    784
#define M_      800
#define N_      8
#define K_      25
#define MN_     6400

// Scratch (allocation-free rule: __device__ globals)
__device__ float g_WbT[(size_t)MN_ * MN_];   // W_b transposed: row j = column j of W_b (163.84 MB)
__device__ float g_A[T_BATCH * M_];          // A[t][m] = W_a @ x_t + b_a
__device__ float g_WdT[M_ * D_IN];           // W_d transposed: row g = column g of W_d

// Monotone float<->uint order mapping (no NaNs in this workload)
__device__ __forceinline__ unsigned fmap(unsigned b) {
    return (b & 0x80000000u) ? ~b : (b | 0x80000000u);
}
__device__ __forceinline__ float funmap(unsigned u) {
    unsigned b = (u & 0x80000000u) ? (u & 0x7FFFFFFFu) : ~u;
    return __uint_as_float(b);
}

// ---------------------------------------------------------------------------
// W_b transpose: 6400x6400, 32x32 tiles
// ---------------------------------------------------------------------------
__global__ void transpose_wb(const float* __restrict__ W) {
    __shared__ float tile[32][33];
    int x  = blockIdx.x * 32 + threadIdx.x;   // column of W
    int y0 = blockIdx.y * 32;
#pragma unroll
    for (int i = threadIdx.y; i < 32; i += 8)
        tile[i][threadIdx.x] = W[(size_t)(y0 + i) * MN_ + x];
    __syncthreads();
    int x2 = blockIdx.y * 32 + threadIdx.x;   // row of W
    int y2 = blockIdx.x * 32;
#pragma unroll
    for (int i = threadIdx.y; i < 32; i += 8)
        g_WbT[(size_t)(y2 + i) * MN_ + x2] = tile[threadIdx.x][i];
}

// ---------------------------------------------------------------------------
// W_d transpose: (784, 800) -> (800, 784), bounds-checked 32x32 tiles
// ---------------------------------------------------------------------------
__global__ void transpose_wd(const float* __restrict__ W) {
    __shared__ float tile[32][33];
    int g0 = blockIdx.x * 32;
    int d0 = blockIdx.y * 32;
#pragma unroll
    for (int i = threadIdx.y; i < 32; i += 8) {
        int d = d0 + i, g = g0 + threadIdx.x;
        if (d < D_IN && g < M_) tile[i][threadIdx.x] = W[d * M_ + g];
    }
    __syncthreads();
#pragma unroll
    for (int i = threadIdx.y; i < 32; i += 8) {
        int g = g0 + i, d = d0 + threadIdx.x;
        if (g < M_ && d < D_IN) g_WdT[g * D_IN + d] = tile[threadIdx.x][i];
    }
}

// ---------------------------------------------------------------------------
// A[t][m] = dot(X[t,:], W_a[m,:]) + b_a[m]   (256x800, K=784) tiled SGEMM
// grid (50, 16), block (16, 16)
// ---------------------------------------------------------------------------
__global__ void gemm_a(const float* __restrict__ X, const float* __restrict__ Wa,
                       const float* __restrict__ ba) {
    __shared__ float xs[16][17];
    __shared__ float ws[16][17];
    int tx = threadIdx.x, ty = threadIdx.y;
    int m = blockIdx.x * 16 + tx;
    int t = blockIdx.y * 16 + ty;
    float acc = 0.0f;
    for (int k0 = 0; k0 < D_IN; k0 += 16) {
        xs[ty][tx] = X[(blockIdx.y * 16 + ty) * D_IN + k0 + tx];
        ws[ty][tx] = Wa[(blockIdx.x * 16 + ty) * D_IN + k0 + tx];
        __syncthreads();
#pragma unroll
        for (int k = 0; k < 16; ++k)
            acc = fmaf(xs[ty][k], ws[tx][k], acc);
        __syncthreads();
    }
    g_A[t * M_ + m] = acc + ba[m];
}

// ---------------------------------------------------------------------------
// Zero the x_b / phi / psi tail of the output (d_out is poisoned)
// ---------------------------------------------------------------------------
__global__ void zero_tail(float* __restrict__ out) {
    int i = blockIdx.x * blockDim.x + threadIdx.x;
    if (i < 3 * MN_) out[T_BATCH * D_IN + i] = 0.0f;
}

// ---------------------------------------------------------------------------
// Main sequential scan: single CTA, 1024 threads, 4 barriers/step
// ---------------------------------------------------------------------------
__global__ void __launch_bounds__(1024, 1)
scan_kernel(const float* __restrict__ bb, const float* __restrict__ bd,
            float* __restrict__ out) {
    __shared__ __align__(16) float sigma_s[MN_];   // 25.6 KB
    __shared__ float lam_s[M_];
    __shared__ unsigned red_min[32];
    __shared__ unsigned long long red_pack[32];
    __shared__ float s_smin;
    __shared__ int   s_jstar;

    const int tid  = threadIdx.x;
    const int lane = tid & 31;
    const int wid  = tid >> 5;

    // Per-thread constants across all 256 steps (indices are time-invariant)
    const int  j4a  = tid;                 // float4 chunk index, covers j = 4*j4a .. +3
    const int  j4b  = tid + 1024;
    const bool hasb = (j4b < MN_ / 4);     // tid < 576
    const float4* bb4 = (const float4*)bb;
    const float4 bbA = bb4[j4a];
    const float4 bbB = hasb ? bb4[j4b] : make_float4(0.f, 0.f, 0.f, 0.f);
    const int aoffA = (4 * j4a) % M_;      // 800 % 4 == 0 -> contiguous float4 in A row
    const int aoffB = (4 * j4b) % M_;
    const float bdv = (tid < D_IN) ? bd[tid] : 0.0f;

    int   jp   = -1;     // active one-hot index of x_b / phi (-1 = zero vectors)
    float phiv = 0.0f;   // phi value at jp

    for (int t = 0; t < T_BATCH; ++t) {
        const float* arow = g_A + t * M_;
        float4 wA = make_float4(0.f, 0.f, 0.f, 0.f);
        float4 wB = make_float4(0.f, 0.f, 0.f, 0.f);
        if (jp >= 0) {
            const float4* wrow = (const float4*)(g_WbT + (size_t)jp * MN_);
            wA = wrow[j4a];
            if (hasb) wB = wrow[j4b];
        }
        const float4 aA = *(const float4*)(arow + aoffA);
        const float4 aB = hasb ? *(const float4*)(arow + aoffB)
                               : make_float4(0.f, 0.f, 0.f, 0.f);

        // sigma = tile(a,N) + W_b[:,jp] + b_b   (same add order as reference)
        float sA[4], sB[4];
        sA[0] = (aA.x + wA.x) + bbA.x;  sA[1] = (aA.y + wA.y) + bbA.y;
        sA[2] = (aA.z + wA.z) + bbA.z;  sA[3] = (aA.w + wA.w) + bbA.w;
        ((float4*)sigma_s)[j4a] = make_float4(sA[0], sA[1], sA[2], sA[3]);
        if (hasb) {
            sB[0] = (aB.x + wB.x) + bbB.x;  sB[1] = (aB.y + wB.y) + bbB.y;
            sB[2] = (aB.z + wB.z) + bbB.z;  sB[3] = (aB.w + wB.w) + bbB.w;
            ((float4*)sigma_s)[j4b] = make_float4(sB[0], sB[1], sB[2], sB[3]);
        }

        // Fused reduction: min(sigma) and argmax(sigma excluding jp, first-index ties)
        unsigned um = 0xFFFFFFFFu;
        unsigned long long pk = 0ull;
#pragma unroll
        for (int i = 0; i < 4; ++i) {
            unsigned u = fmap(__float_as_uint(sA[i]));
            um = min(um, u);
            int j = 4 * j4a + i;
            if (j != jp)
                pk = max(pk, ((unsigned long long)u << 13) | (unsigned)(MN_ - 1 - j));
        }
        if (hasb) {
#pragma unroll
            for (int i = 0; i < 4; ++i) {
                unsigned u = fmap(__float_as_uint(sB[i]));
                um = min(um, u);
                int j = 4 * j4b + i;
                if (j != jp)
                    pk = max(pk, ((unsigned long long)u << 13) | (unsigned)(MN_ - 1 - j));
            }
        }
        um = __reduce_min_sync(0xFFFFFFFFu, um);
#pragma unroll
        for (int o = 16; o; o >>= 1)
            pk = max(pk, __shfl_xor_sync(0xFFFFFFFFu, pk, o));
        if (lane == 0) { red_min[wid] = um; red_pack[wid] = pk; }
        __syncthreads();                                       // bar1
        if (wid == 0) {
            unsigned um2 = __reduce_min_sync(0xFFFFFFFFu, red_min[lane]);
            unsigned long long pk2 = red_pack[lane];
#pragma unroll
            for (int o = 16; o; o >>= 1)
                pk2 = max(pk2, __shfl_xor_sync(0xFFFFFFFFu, pk2, o));
            if (lane == 0) {
                float smin = funmap(um2);
                int M1 = MN_ - 1 - (int)(pk2 & 0x1FFFull);
                int jstar = M1;
                if (jp >= 0) {
                    // pi is monotone in sigma except the single jp element
                    float v1 = (sigma_s[M1] - smin) + 1.0f;
                    float pv = (1.0f - phiv) * ((sigma_s[jp] - smin) + 1.0f);
                    if (pv > v1)       jstar = jp;
                    else if (pv == v1) jstar = (jp < M1) ? jp : M1;
                }
                s_smin  = smin;
                s_jstar = jstar;
            }
        }
        __syncthreads();                                       // bar2
        const float smin  = s_smin;
        const int   jstar = s_jstar;
        const int   g     = jstar >> 3;      // reshape-group (for W_d column)
        const int   q     = jstar % M_;      // tile-group (for m_lam mask)

        // Speculative W_d column load — latency hidden behind lam/count phase
        const float wd = (tid < D_IN) ? g_WdT[g * D_IN + tid] : 0.0f;
        const float sj = sigma_s[jstar];

        // lam[m] = max_n pi[m*8+n], computed with the exact reference pi formula
        if (tid < M_) {
            float lm = -3.402823466e38f;
#pragma unroll
            for (int n = 0; n < 8; ++n) {
                int j = tid * 8 + n;
                float p = (sigma_s[j] - smin) + 1.0f;
                if (j == jp) p *= (1.0f - phiv);
                lm = fmaxf(lm, p);
            }
            lam_s[tid] = lm;
        }
        __syncthreads();                                       // bar3
        const float lamq = lam_s[q];
        int flag = 0;
        if (tid < M_ && tid != q) {
            float lm = lam_s[tid];
            flag = (lm > lamq) || (lm == lamq && tid < q);
        }
        const int cnt = __syncthreads_count(flag);             // bar4 (rank of q in lam)

        const float tt   = tanhf(sj);
        const float yval = (cnt < K_) ? tt : 0.0f;             // m_lam gate
        const float gval = (yval > 0.0f) ? yval : 0.0f;        // relu'd group max of y

        // preds[t] = W_d @ groupmax(y) + b_d  (single column, or just b_d)
        if (tid < D_IN)
            out[t * D_IN + tid] = (gval > 0.0f) ? (wd * gval + bdv) : bdv;

        // Next state (uniform across threads — no extra barrier needed;
        // next sigma_s writes are already fenced by bar4)
        if (yval > 0.0f) { jp = jstar; phiv = yval; }
        else             { jp = -1;    phiv = 0.0f; }
    }

    // Final outputs: x_b (one-hot, value exactly 1.0), phi, psis[-1]
    if (tid == 0 && jp >= 0) {
        out[T_BATCH * D_IN + jp]            = 1.0f;   // x_b
        out[T_BATCH * D_IN + MN_ + jp]      = phiv;   // phi
        out[T_BATCH * D_IN + 2 * MN_ + jp]  = phiv;   // psis[-1]
    }
}

// ---------------------------------------------------------------------------
extern "C" void kernel_launch(void* const* d_in, const int* in_sizes, int n_in,
                              void* d_out, int out_size) {
    const float* X  = (const float*)d_in[0];   // batch_x (256, 784)
    const float* Wa = (const float*)d_in[1];   // (800, 784)
    const float* ba = (const float*)d_in[2];   // (800,)
    const float* Wb = (const float*)d_in[3];   // (6400, 6400)
    const float* bb = (const float*)d_in[4];   // (6400,)
    const float* Wd = (const float*)d_in[5];   // (784, 800)
    const float* bd = (const float*)d_in[6];   // (784,)
    float* out = (float*)d_out;

    transpose_wb<<<dim3(MN_ / 32, MN_ / 32), dim3(32, 8)>>>(Wb);
    transpose_wd<<<dim3(M_ / 32, (D_IN + 31) / 32), dim3(32, 8)>>>(Wd);
    gemm_a<<<dim3(M_ / 16, T_BATCH / 16), dim3(16, 16)>>>(X, Wa, ba);
    zero_tail<<<(3 * MN_ + 255) / 256, 256>>>(out);
    scan_kernel<<<1, 1024>>>(bb, bd, out);
}